// round 3
// baseline (speedup 1.0000x reference)
#include <cuda_runtime.h>
#include <cstdint>

// VariableGroupNorm: x[N,C,H,W] fp32, ragged groups (channels contiguous per group),
// per-(n,g) mean/var -> y = x*scale + shift.
// N=32, C=256, H=W=56, G=32. Group sizes alternate 4/12 -> each adjacent PAIR of
// groups is 16 channels: one CTA per (n, pair) gives 512 perfectly uniform CTAs.

#define NB 32
#define CC 256
#define GG 32
#define NPAIR (GG / 2)        // 16
#define HW 3136               // 56*56
#define HW4 784               // float4 per channel
#define VGN_EPS 1e-5f
#define TPB 256

// Decode pair p: start channel of group 2p, sizes of groups 2p and 2p+1.
// Defensive dtype handling: int32 if the 32 int32 reads sum to C, else int64.
__device__ __forceinline__ void decode_pair(const void* __restrict__ gs_raw,
                                            int p, int& c0, int& gsA, int& gsB) {
    const int* p32 = (const int*)gs_raw;
    long long s32 = 0;
    #pragma unroll
    for (int i = 0; i < GG; i++) s32 += __ldg(&p32[i]);
    int start = 0, a = 0, b = 0;
    const int gA = 2 * p, gB = 2 * p + 1;
    if (s32 == (long long)CC) {
        #pragma unroll
        for (int i = 0; i < GG; i++) {
            int v = __ldg(&p32[i]);
            if (i < gA) start += v;
            if (i == gA) a = v;
            if (i == gB) b = v;
        }
    } else {
        const long long* p64 = (const long long*)gs_raw;
        #pragma unroll
        for (int i = 0; i < GG; i++) {
            int v = (int)__ldg(&p64[i]);
            if (i < gA) start += v;
            if (i == gA) a = v;
            if (i == gB) b = v;
        }
    }
    c0 = start; gsA = a; gsB = b;
}

// Sum / sumsq over nv float4, 4-wide batched.
__device__ __forceinline__ void stats_range(const float4* __restrict__ px, int nv,
                                            float& s_out, float& ss_out) {
    float s = 0.f, ss = 0.f;
    int i = threadIdx.x;
    for (; i + 3 * TPB < nv; i += 4 * TPB) {
        float4 v[4];
        #pragma unroll
        for (int u = 0; u < 4; u++) v[u] = px[i + u * TPB];
        #pragma unroll
        for (int u = 0; u < 4; u++) {
            s  += (v[u].x + v[u].y) + (v[u].z + v[u].w);
            ss += v[u].x * v[u].x + v[u].y * v[u].y
                + v[u].z * v[u].z + v[u].w * v[u].w;
        }
    }
    for (; i < nv; i += TPB) {
        const float4 v = px[i];
        s  += (v.x + v.y) + (v.z + v.w);
        ss += v.x * v.x + v.y * v.y + v.z * v.z + v.w * v.w;
    }
    s_out = s; ss_out = ss;
}

// y = x*sc + sf over nv float4; last-use reads, evict-first stores.
__device__ __forceinline__ void apply_range(const float4* __restrict__ px,
                                            float4* __restrict__ po, int nv,
                                            float sc, float sf) {
    int i = threadIdx.x;
    for (; i + 3 * TPB < nv; i += 4 * TPB) {
        float4 v[4];
        #pragma unroll
        for (int u = 0; u < 4; u++) v[u] = __ldcs(px + i + u * TPB);
        #pragma unroll
        for (int u = 0; u < 4; u++) {
            v[u].x = fmaf(v[u].x, sc, sf);
            v[u].y = fmaf(v[u].y, sc, sf);
            v[u].z = fmaf(v[u].z, sc, sf);
            v[u].w = fmaf(v[u].w, sc, sf);
            __stcs(po + i + u * TPB, v[u]);
        }
    }
    for (; i < nv; i += TPB) {
        float4 v = __ldcs(px + i);
        v.x = fmaf(v.x, sc, sf);
        v.y = fmaf(v.y, sc, sf);
        v.z = fmaf(v.z, sc, sf);
        v.w = fmaf(v.w, sc, sf);
        __stcs(po + i, v);
    }
}

__global__ void __launch_bounds__(TPB)
vgn_kernel(const float* __restrict__ x,
           const float* __restrict__ gamma,
           const float* __restrict__ beta,
           float* __restrict__ out,
           const void* __restrict__ gs_raw) {
    const int item = blockIdx.x;             // 0 .. N*NPAIR-1 (512)
    const int n  = item & (NB - 1);
    const int p  = item >> 5;
    int c0, gsA, gsB;
    decode_pair(gs_raw, p, c0, gsA, gsB);
    const int gA = 2 * p, gB = gA + 1;

    const size_t base = ((size_t)n * CC + (size_t)c0) * HW;
    const float4* __restrict__ pxA = (const float4*)(x + base);
    float4* __restrict__ poA       = (float4*)(out + base);
    const int nvA = gsA * HW4;
    const int nvB = gsB * HW4;
    const float4* __restrict__ pxB = pxA + nvA;
    float4* __restrict__ poB       = poA + nvA;

    // ---- pass 1: stats for both groups ----
    float sA, ssA, sB, ssB;
    stats_range(pxA, nvA, sA, ssA);
    stats_range(pxB, nvB, sB, ssB);

    // block reduce 4 values (8 warps)
    #pragma unroll
    for (int o = 16; o > 0; o >>= 1) {
        sA  += __shfl_xor_sync(0xFFFFFFFFu, sA,  o);
        ssA += __shfl_xor_sync(0xFFFFFFFFu, ssA, o);
        sB  += __shfl_xor_sync(0xFFFFFFFFu, sB,  o);
        ssB += __shfl_xor_sync(0xFFFFFFFFu, ssB, o);
    }
    __shared__ float4 shw[8];
    __shared__ float4 sh_param;              // scA, sfA, scB, sfB
    const int wid = threadIdx.x >> 5, lid = threadIdx.x & 31;
    if (lid == 0) shw[wid] = make_float4(sA, ssA, sB, ssB);
    __syncthreads();
    if (threadIdx.x == 0) {
        float tsA = 0.f, tssA = 0.f, tsB = 0.f, tssB = 0.f;
        #pragma unroll
        for (int w = 0; w < 8; w++) {
            tsA += shw[w].x; tssA += shw[w].y;
            tsB += shw[w].z; tssB += shw[w].w;
        }
        const float invA  = 1.0f / (float)(gsA * HW);
        const float meanA = tsA * invA;
        const float varA  = tssA * invA - meanA * meanA;
        const float scA   = __ldg(&gamma[gA]) * rsqrtf(varA + VGN_EPS);
        const float invB  = 1.0f / (float)(gsB * HW);
        const float meanB = tsB * invB;
        const float varB  = tssB * invB - meanB * meanB;
        const float scB   = __ldg(&gamma[gB]) * rsqrtf(varB + VGN_EPS);
        sh_param = make_float4(scA, fmaf(-meanA, scA, __ldg(&beta[gA])),
                               scB, fmaf(-meanB, scB, __ldg(&beta[gB])));
    }
    __syncthreads();
    const float4 prm = sh_param;

    // ---- pass 2: normalize both groups (reads served from L2) ----
    apply_range(pxA, poA, nvA, prm.x, prm.y);
    apply_range(pxB, poB, nvB, prm.z, prm.w);
}

extern "C" void kernel_launch(void* const* d_in, const int* in_sizes, int n_in,
                              void* d_out, int out_size) {
    const float* x     = (const float*)d_in[0];
    const float* gamma = (const float*)d_in[1];
    const float* beta  = (const float*)d_in[2];
    const void*  gsz   = d_in[3];
    float* out = (float*)d_out;

    vgn_kernel<<<NB * NPAIR, TPB>>>(x, gamma, beta, out, gsz);
}